// round 16
// baseline (speedup 1.0000x reference)
#include <cuda_runtime.h>
#include <cuda_bf16.h>
#include <cstdint>

// VectorQuantizer: x (16,2048,256) f32, codebook (1024,256) f32.
// Outputs (concatenated f32 in d_out):
//   [0, N*D)        quantized = x + (cb[idx] - x)
//   [N*D, N*D+N)    indices (as float)
//   [N*D+N]         commitment loss = mean((cb[idx]-x)^2)
//
// Hybrid distance pass: HMMA (tensor pipe, bf16+margin candidates) blocks and
// FFMA2 (fma pipe, exact fp32) blocks run concurrently in ONE kernel, split by
// blockIdx. Exact fp32 refine (validated rounding sequence, lowest-index ties)
// + fused gather + loss partials.

#define DDIM    256
#define KCODES  1024
#define NROWS   32768

// HMMA sub-grid: 136 blocks x 128 rows = rows [0, 17408)
#define GH      136
#define BM      128
#define BN      128
#define TS      72
#define CAND_CAP 16
#define MARGIN  6e-3f

// FFMA2 sub-grid: 240 blocks x 64 rows = rows [17408, 32768)
#define RH      (GH * BM)        // 17408
#define GF      240
#define BMF     64
#define BKF     16
#define XS_STRIDE 17
#define ES_STRIDE 130

__device__ float  g_sx[NROWS];
__device__ float  g_se[KCODES];
__device__ double g_part[NROWS / 8];
__device__ __nv_bfloat16 g_xb[(size_t)NROWS * DDIM];
__device__ __nv_bfloat16 g_eb[(size_t)KCODES * DDIM];
__device__ int    g_cnt[NROWS];
__device__ int    g_cand[NROWS * CAND_CAP];

// ---------------------------------------------------------------------------
// Row sum-of-squares for x and codebook + bf16 conversion. One warp per row.
// ---------------------------------------------------------------------------
__global__ void stats_kernel(const float* __restrict__ x,
                             const float* __restrict__ cb,
                             int N, int K) {
    int warp = (blockIdx.x * blockDim.x + threadIdx.x) >> 5;
    int lane = threadIdx.x & 31;
    if (warp >= N + K) return;
    const float* src;
    __nv_bfloat16* dst;
    if (warp < N) { src = x  + (size_t)warp * DDIM;       dst = g_xb + (size_t)warp * DDIM; }
    else          { src = cb + (size_t)(warp - N) * DDIM; dst = g_eb + (size_t)(warp - N) * DDIM; }
    float s = 0.0f;
#pragma unroll
    for (int i = 0; i < DDIM / 32; i++) {
        float v = src[lane + 32 * i];
        s = fmaf(v, v, s);
        dst[lane + 32 * i] = __float2bfloat16(v);
    }
#pragma unroll
    for (int off = 16; off; off >>= 1)
        s += __shfl_down_sync(0xffffffffu, s, off);
    if (lane == 0) {
        if (warp < N) g_sx[warp] = s;
        else          g_se[warp - N] = s;
    }
}

// ---------------------------------------------------------------------------
// Shared-memory overlays for the two block flavors.
// ---------------------------------------------------------------------------
struct SmemH {
    __nv_bfloat16 Xs[BM * TS];
    __nv_bfloat16 Es[BN * TS];
    float    sxs[BM];
    float    ses[BN];
    unsigned rmin[BM];
    int      cnt[BM];
    int      lst[BM * CAND_CAP];
};
struct SmemF {
    float Xs[BMF * XS_STRIDE];
    float Es[BKF * ES_STRIDE];
    float red_v[BMF * 16];
    int   red_i[BMF * 16];
};
#define SMEM_MAX (sizeof(SmemH) > sizeof(SmemF) ? sizeof(SmemH) : sizeof(SmemF))

// ---------------------------------------------------------------------------
// HMMA flavor (validated R12 body): 8 warps as 4M x 2N, 128x128 tile,
// bf16 mma.sync m16n8k16, manual fragment LDS, margin candidates.
// ---------------------------------------------------------------------------
__device__ void dist_hmma(char* smraw, int blk) {
    SmemH& S = *reinterpret_cast<SmemH*>(smraw);
    const int tid  = threadIdx.x;
    const int lane = tid & 31;
    const int wid  = tid >> 5;
    const int wm   = wid >> 1;        // 0..3 along M (32 rows each)
    const int wn   = wid & 1;         // 0..1 along N (64 codes each)
    const int r0   = blk * BM;

    const int gr = lane >> 2;
    const int gj = lane & 3;

    if (tid < BM) {
        S.sxs[tid]  = g_sx[r0 + tid];
        S.rmin[tid] = 0x7f7fffffu;
        S.cnt[tid]  = 0;
    }

    for (int n0 = 0; n0 < KCODES; n0 += BN) {
        __syncthreads();
        if (tid < BN) S.ses[tid] = g_se[n0 + tid];

        float acc[2][8][4];
#pragma unroll
        for (int mi = 0; mi < 2; mi++)
#pragma unroll
            for (int ni = 0; ni < 8; ni++)
#pragma unroll
                for (int q = 0; q < 4; q++) acc[mi][ni][q] = 0.0f;

        for (int kt = 0; kt < 4; kt++) {
            const int kk = kt * 64;
            __syncthreads();
#pragma unroll
            for (int p = 0; p < 4; p++) {
                int idx = tid + p * 256;
                int r = idx >> 3, q = idx & 7;
                *(uint4*)(S.Xs + r * TS + q * 8) =
                    *(const uint4*)(g_xb + (size_t)(r0 + r) * DDIM + kk + q * 8);
                *(uint4*)(S.Es + r * TS + q * 8) =
                    *(const uint4*)(g_eb + (size_t)(n0 + r) * DDIM + kk + q * 8);
            }
            __syncthreads();

#pragma unroll
            for (int ks = 0; ks < 4; ks++) {
                const int kb = ks * 16;
                unsigned a[2][4];
#pragma unroll
                for (int mi = 0; mi < 2; mi++) {
                    const __nv_bfloat16* ar =
                        S.Xs + (wm * 32 + mi * 16 + gr) * TS + kb + 2 * gj;
                    a[mi][0] = *(const unsigned*)(ar);
                    a[mi][1] = *(const unsigned*)(ar + 8 * TS);
                    a[mi][2] = *(const unsigned*)(ar + 8);
                    a[mi][3] = *(const unsigned*)(ar + 8 * TS + 8);
                }
#pragma unroll
                for (int ni = 0; ni < 8; ni++) {
                    const __nv_bfloat16* br =
                        S.Es + (wn * 64 + ni * 8 + gr) * TS + kb + 2 * gj;
                    unsigned b0 = *(const unsigned*)(br);
                    unsigned b1 = *(const unsigned*)(br + 8);
#pragma unroll
                    for (int mi = 0; mi < 2; mi++) {
                        asm volatile(
                            "mma.sync.aligned.m16n8k16.row.col.f32.bf16.bf16.f32 "
                            "{%0,%1,%2,%3},{%4,%5,%6,%7},{%8,%9},{%0,%1,%2,%3};"
                            : "+f"(acc[mi][ni][0]), "+f"(acc[mi][ni][1]),
                              "+f"(acc[mi][ni][2]), "+f"(acc[mi][ni][3])
                            : "r"(a[mi][0]), "r"(a[mi][1]), "r"(a[mi][2]), "r"(a[mi][3]),
                              "r"(b0), "r"(b1));
                    }
                }
            }
        }

        const int gc = gj * 2;
#pragma unroll
        for (int mi = 0; mi < 2; mi++) {
#pragma unroll
            for (int h = 0; h < 2; h++) {
                int row = wm * 32 + mi * 16 + gr + 8 * h;
                float t0 = S.sxs[row];
                float dm = 3.4e38f;
#pragma unroll
                for (int ni = 0; ni < 8; ni++) {
                    int col = wn * 64 + ni * 8 + gc;
                    float d0 = fmaf(-2.0f, acc[mi][ni][2*h],   t0 + S.ses[col]);
                    float d1 = fmaf(-2.0f, acc[mi][ni][2*h+1], t0 + S.ses[col+1]);
                    acc[mi][ni][2*h]   = d0;
                    acc[mi][ni][2*h+1] = d1;
                    dm = fminf(dm, fminf(d0, d1));
                }
                atomicMin(&S.rmin[row], __float_as_uint(dm));
            }
        }
        __syncthreads();
#pragma unroll
        for (int mi = 0; mi < 2; mi++) {
#pragma unroll
            for (int h = 0; h < 2; h++) {
                int row = wm * 32 + mi * 16 + gr + 8 * h;
                float thr = __uint_as_float(S.rmin[row]) + MARGIN;
#pragma unroll
                for (int ni = 0; ni < 8; ni++) {
#pragma unroll
                    for (int q = 0; q < 2; q++) {
                        float d = acc[mi][ni][2*h + q];
                        if (d <= thr) {
                            int pos = atomicAdd(&S.cnt[row], 1);
                            if (pos < CAND_CAP)
                                S.lst[row * CAND_CAP + pos] = n0 + wn * 64 + ni * 8 + gc + q;
                        }
                    }
                }
            }
        }
    }

    __syncthreads();
    if (tid < BM) {
        int row = r0 + tid;
        int c = S.cnt[tid];
        g_cnt[row] = c;
        int m = c < CAND_CAP ? c : CAND_CAP;
        for (int j = 0; j < m; j++)
            g_cand[row * CAND_CAP + j] = S.lst[tid * CAND_CAP + j];
    }
}

// ---------------------------------------------------------------------------
// FFMA2 flavor (validated R1 body): 64 rows x full K, exact fp32 via packed
// fma.rn.f32x2, exact running argmin with lowest-index ties. Emits cnt=1 +
// the exact winner as the sole candidate.
// ---------------------------------------------------------------------------
__device__ void dist_ffma2(char* smraw, const float* __restrict__ x,
                           const float* __restrict__ cb, int blk) {
    SmemF& S = *reinterpret_cast<SmemF*>(smraw);
    const int tid = threadIdx.x;
    const int tx  = tid & 15;
    const int ty  = tid >> 4;
    const int r0  = RH + blk * BMF;

    float best[4];
    int   bidx[4];
#pragma unroll
    for (int i = 0; i < 4; i++) { best[i] = 3.4e38f; bidx[i] = 0; }

    float sxr[4];
#pragma unroll
    for (int i = 0; i < 4; i++) sxr[i] = g_sx[r0 + ty * 4 + i];

    for (int n0 = 0; n0 < KCODES; n0 += 128) {
        unsigned long long acc[4][4];
#pragma unroll
        for (int i = 0; i < 4; i++)
#pragma unroll
            for (int j = 0; j < 4; j++) acc[i][j] = 0ull;

        for (int kk = 0; kk < DDIM; kk += BKF) {
            __syncthreads();
#pragma unroll
            for (int p = 0; p < (BMF * BKF) / 256; p++) {      // 4 iters
                int idx = tid + p * 256;
                int row = idx >> 4, dd = idx & 15;
                S.Xs[row * XS_STRIDE + dd] = x[(size_t)(r0 + row) * DDIM + kk + dd];
            }
#pragma unroll
            for (int p = 0; p < (128 * BKF) / 256; p++) {      // 8 iters
                int idx = tid + p * 256;
                int dd = idx & 15, col = idx >> 4;
                S.Es[dd * ES_STRIDE + col] = cb[(size_t)(n0 + col) * DDIM + kk + dd];
            }
            __syncthreads();

#pragma unroll
            for (int dd = 0; dd < BKF; dd++) {
                unsigned long long a2[4], b2[4];
#pragma unroll
                for (int i = 0; i < 4; i++) {
                    unsigned int ua = __float_as_uint(S.Xs[(ty * 4 + i) * XS_STRIDE + dd]);
                    asm("mov.b64 %0, {%1, %1};" : "=l"(a2[i]) : "r"(ua));
                }
#pragma unroll
                for (int j = 0; j < 4; j++)
                    b2[j] = *reinterpret_cast<const unsigned long long*>(
                        &S.Es[dd * ES_STRIDE + tx * 2 + 32 * j]);
#pragma unroll
                for (int i = 0; i < 4; i++)
#pragma unroll
                    for (int j = 0; j < 4; j++)
                        asm("fma.rn.f32x2 %0, %1, %2, %0;"
                            : "+l"(acc[i][j]) : "l"(a2[i]), "l"(b2[j]));
            }
        }

#pragma unroll
        for (int i = 0; i < 4; i++) {
#pragma unroll
            for (int j = 0; j < 4; j++) {
                unsigned int lo, hi;
                asm("mov.b64 {%0, %1}, %2;" : "=r"(lo), "=r"(hi) : "l"(acc[i][j]));
                int k0 = n0 + 32 * j + tx * 2;
                {
                    float t  = sxr[i] + g_se[k0];
                    float dv = fmaf(-2.0f, __uint_as_float(lo), t);
                    if (dv < best[i]) { best[i] = dv; bidx[i] = k0; }
                }
                {
                    float t  = sxr[i] + g_se[k0 + 1];
                    float dv = fmaf(-2.0f, __uint_as_float(hi), t);
                    if (dv < best[i]) { best[i] = dv; bidx[i] = k0 + 1; }
                }
            }
        }
    }

    __syncthreads();
#pragma unroll
    for (int i = 0; i < 4; i++) {
        S.red_v[(ty * 4 + i) * 16 + tx] = best[i];
        S.red_i[(ty * 4 + i) * 16 + tx] = bidx[i];
    }
    __syncthreads();

    if (tid < BMF) {
        float bv = S.red_v[tid * 16];
        int   bi = S.red_i[tid * 16];
#pragma unroll
        for (int t = 1; t < 16; t++) {
            float v  = S.red_v[tid * 16 + t];
            int   id = S.red_i[tid * 16 + t];
            if (v < bv || (v == bv && id < bi)) { bv = v; bi = id; }
        }
        int row = r0 + tid;
        g_cnt[row] = 1;
        g_cand[row * CAND_CAP] = bi;
    }
}

__global__ __launch_bounds__(256, 2)
void dist_hybrid(const float* __restrict__ x, const float* __restrict__ cb) {
    __shared__ __align__(16) char smraw[SMEM_MAX];
    if (blockIdx.x < GH) dist_hmma(smraw, blockIdx.x);
    else                 dist_ffma2(smraw, x, cb, blockIdx.x - GH);
}

// ---------------------------------------------------------------------------
// Exact refine + fused gather. One warp per row. Refine is bit-identical to
// the validated fp32 formula: serial fmaf dot, d = fmaf(-2,dot,sx+se),
// lowest-index ties. cnt==1 rows resolve trivially to their exact winner.
// Then gather quantized = x + (q - x) and emit per-BLOCK loss partials.
// ---------------------------------------------------------------------------
__device__ __forceinline__ float exact_dist(const float4* __restrict__ xr,
                                            const float* __restrict__ cb,
                                            float sx, int k) {
    const float4* er = (const float4*)(cb + (size_t)k * DDIM);
    float dot = 0.0f;
#pragma unroll 8
    for (int i = 0; i < DDIM / 4; i++) {
        float4 a = xr[i], b = er[i];
        dot = fmaf(a.x, b.x, dot);
        dot = fmaf(a.y, b.y, dot);
        dot = fmaf(a.z, b.z, dot);
        dot = fmaf(a.w, b.w, dot);
    }
    return fmaf(-2.0f, dot, sx + g_se[k]);
}

__global__ void refine_gather_kernel(const float* __restrict__ x,
                                     const float* __restrict__ cb,
                                     float* __restrict__ out_idx_f,
                                     float* __restrict__ out_q) {
    __shared__ double warp_s[8];
    int warp_in_blk = threadIdx.x >> 5;
    int row  = blockIdx.x * 8 + warp_in_blk;
    int lane = threadIdx.x & 31;

    const float4* xr = (const float4*)(x + (size_t)row * DDIM);
    float sx = g_sx[row];
    int c = g_cnt[row];

    float bd = 3.4e38f;
    int   bk = 0x7fffffff;
    if (c <= CAND_CAP) {
        if (lane < c) {
            int k = g_cand[row * CAND_CAP + lane];
            bd = exact_dist(xr, cb, sx, k);
            bk = k;
        }
    } else {
        for (int k = lane; k < KCODES; k += 32) {
            float d = exact_dist(xr, cb, sx, k);
            if (d < bd || (d == bd && k < bk)) { bd = d; bk = k; }
        }
    }
#pragma unroll
    for (int off = 16; off; off >>= 1) {
        float od = __shfl_down_sync(0xffffffffu, bd, off);
        int   ok = __shfl_down_sync(0xffffffffu, bk, off);
        if (od < bd || (od == bd && ok < bk)) { bd = od; bk = ok; }
    }
    bk = __shfl_sync(0xffffffffu, bk, 0);
    if (lane == 0) out_idx_f[row] = (float)bk;

    const float4* qr = (const float4*)(cb + (size_t)bk * DDIM);
    float4* orow = (float4*)(out_q + (size_t)row * DDIM);
    double s = 0.0;
#pragma unroll
    for (int i = 0; i < 2; i++) {
        float4 xv = xr[lane + 32 * i];
        float4 qv = qr[lane + 32 * i];
        float4 o;
        float e0 = qv.x - xv.x; o.x = xv.x + e0; s += (double)e0 * e0;
        float e1 = qv.y - xv.y; o.y = xv.y + e1; s += (double)e1 * e1;
        float e2 = qv.z - xv.z; o.z = xv.z + e2; s += (double)e2 * e2;
        float e3 = qv.w - xv.w; o.w = xv.w + e3; s += (double)e3 * e3;
        orow[lane + 32 * i] = o;
    }
#pragma unroll
    for (int off = 16; off; off >>= 1)
        s += __shfl_down_sync(0xffffffffu, s, off);
    if (lane == 0) warp_s[warp_in_blk] = s;
    __syncthreads();
    if (threadIdx.x == 0) {
        double bs = 0.0;
#pragma unroll
        for (int w = 0; w < 8; w++) bs += warp_s[w];
        g_part[blockIdx.x] = bs;
    }
}

__global__ void finalize_kernel(float* __restrict__ out_loss,
                                int nblocks, long long ND) {
    __shared__ double sm[256];
    double s = 0.0;
    for (int i = threadIdx.x; i < nblocks; i += 256) s += g_part[i];
    sm[threadIdx.x] = s;
    __syncthreads();
    for (int off = 128; off; off >>= 1) {
        if (threadIdx.x < off) sm[threadIdx.x] += sm[threadIdx.x + off];
        __syncthreads();
    }
    if (threadIdx.x == 0) *out_loss = (float)(sm[0] / (double)ND);
}

// ---------------------------------------------------------------------------
extern "C" void kernel_launch(void* const* d_in, const int* in_sizes, int n_in,
                              void* d_out, int out_size) {
    const float* x  = (const float*)d_in[0];
    const float* cb = (const float*)d_in[1];
    int N = in_sizes[0] / DDIM;   // 32768
    int K = in_sizes[1] / DDIM;   // 1024

    float* out   = (float*)d_out;
    float* out_q = out;
    float* out_i = out + (size_t)N * DDIM;
    float* out_l = out + (size_t)N * DDIM + N;

    stats_kernel<<<(N + K + 7) / 8, 256>>>(x, cb, N, K);
    dist_hybrid<<<GH + GF, 256>>>(x, cb);
    int rg_blocks = N / 8;   // 4096
    refine_gather_kernel<<<rg_blocks, 256>>>(x, cb, out_i, out_q);
    finalize_kernel<<<1, 256>>>(out_l, rg_blocks, (long long)N * DDIM);
}